// round 2
// baseline (speedup 1.0000x reference)
#include <cuda_runtime.h>
#include <cstdint>

// ---------------------------------------------------------------------------
// 4-layer LIF SNN scan (B=4096, S=H=256, T=50, A=2) on sm_103a.
// R2: packed fp32 FFMA2 (fma.rn.f32x2) over column pairs, 448-thread blocks,
// MB=28 rows/block (grid=147, one balanced wave), all state resident.
// Numerics: per-(b,j) single accumulator, strictly ascending k, rn at every
// step -> bit-identical spike trajectory to the scalar reference kernel.
// ---------------------------------------------------------------------------

namespace {

constexpr int Bb = 4096;
constexpr int Ss = 256;
constexpr int Tt = 50;
constexpr int Hh = 256;
constexpr int Aa = 2;

constexpr int MB      = 28;
constexpr int THREADS = 448;               // 64 colgroups(4 cols) x 7 rowgroups(4 rows)
constexpr int NBLK    = (Bb + MB - 1) / MB; // 147
constexpr int PS      = 256;               // pre/spike row stride

constexpr float CDECAY = 0.5f;
constexpr float VDECAY = 0.75f;
constexpr float VTH    = 0.5f;

// smem layout (floats)
constexpr int OFF_XE = 0;                      // x tiles   [2][MB][PS]
constexpr int OFF_SA = OFF_XE + 2 * MB * PS;   // spike A   [MB][PS]
constexpr int OFF_SB = OFF_SA + MB * PS;       // spike B   [MB][PS]
constexpr int OFF_US = OFF_SB + MB * PS;       // u state   [3][MB][Hh]
constexpr int OFF_W4 = OFF_US + 3 * MB * Hh;   // w4        [Hh*Aa]
constexpr int SMEM_FLOATS = OFF_W4 + Hh * Aa;
constexpr int SMEM_BYTES  = SMEM_FLOATS * 4;   // 202,752 B

}  // namespace

// Duplicate one fp32 into both lanes of an f32x2 operand.
__device__ __forceinline__ uint64_t dup2(float x) {
    uint64_t r;
    asm("mov.b64 %0, {%1, %1};" : "=l"(r) : "f"(x));
    return r;
}

// Packed dual fp32 FMA: per-lane round-to-nearest, lanes independent.
__device__ __forceinline__ void ffma2(uint64_t& c, uint64_t a, uint64_t b) {
    asm("fma.rn.f32x2 %0, %1, %2, %0;" : "+l"(c) : "l"(a), "l"(b));
}

__device__ __forceinline__ float2 unpk(uint64_t v) {
    float2 r;
    asm("mov.b64 {%0, %1}, %2;" : "=f"(r.x), "=f"(r.y) : "l"(v));
    return r;
}

// One LIF layer tile: thread owns cols [j0, j0+4) x rows [row0, row0+4).
__device__ __forceinline__ void lif4x4(
    const float* __restrict__ W,     // [Hh][Hh] row-major (row k, col j)
    const float4 bias,               // b[j0..j0+4)
    const float* __restrict__ pre,   // smem [MB][PS]
    float*       __restrict__ spk,   // smem [MB][PS]
    float*       __restrict__ u_s,   // smem [MB][Hh] (this layer)
    float (&vm)[4][4],               // (v*0.75)*(1-s) carry, [row][col]
    int row0, int j0)
{
    uint64_t acc[4][2];
#pragma unroll
    for (int r = 0; r < 4; ++r) { acc[r][0] = 0ull; acc[r][1] = 0ull; }

    const float* wp = W + j0;

#pragma unroll 2
    for (int k4 = 0; k4 < Hh / 4; ++k4) {
        ulonglong2 wk[4];  // wk[kk].x = (w_j0, w_j0+1), .y = (w_j0+2, w_j0+3)
#pragma unroll
        for (int kk = 0; kk < 4; ++kk)
            wk[kk] = *reinterpret_cast<const ulonglong2*>(wp + (k4 * 4 + kk) * Hh);

#pragma unroll
        for (int r = 0; r < 4; ++r) {
            const float4 p = *reinterpret_cast<const float4*>(pre + (row0 + r) * PS + k4 * 4);
            const uint64_t d0 = dup2(p.x);
            ffma2(acc[r][0], d0, wk[0].x);
            ffma2(acc[r][1], d0, wk[0].y);
            const uint64_t d1 = dup2(p.y);
            ffma2(acc[r][0], d1, wk[1].x);
            ffma2(acc[r][1], d1, wk[1].y);
            const uint64_t d2 = dup2(p.z);
            ffma2(acc[r][0], d2, wk[2].x);
            ffma2(acc[r][1], d2, wk[2].y);
            const uint64_t d3 = dup2(p.w);
            ffma2(acc[r][0], d3, wk[3].x);
            ffma2(acc[r][1], d3, wk[3].y);
        }
    }

#pragma unroll
    for (int r = 0; r < 4; ++r) {
        const int b = row0 + r;
        const float4 uo = *reinterpret_cast<const float4*>(u_s + b * Hh + j0);
        const float2 a01 = unpk(acc[r][0]);
        const float2 a23 = unpk(acc[r][1]);
        float cur[4], s[4];
        const float am[4] = {a01.x, a01.y, a23.x, a23.y};
        const float uu[4] = {uo.x, uo.y, uo.z, uo.w};
        const float bb[4] = {bias.x, bias.y, bias.z, bias.w};
#pragma unroll
        for (int c = 0; c < 4; ++c) {
            cur[c] = __fadd_rn(__fadd_rn(__fmul_rn(uu[c], CDECAY), am[c]), bb[c]);
            const float volt = __fadd_rn(vm[r][c], cur[c]);
            s[c] = (volt > VTH) ? 1.0f : 0.0f;
            vm[r][c] = __fmul_rn(__fmul_rn(volt, VDECAY), __fsub_rn(1.0f, s[c]));
        }
        *reinterpret_cast<float4*>(u_s + b * Hh + j0) = make_float4(cur[0], cur[1], cur[2], cur[3]);
        *reinterpret_cast<float4*>(spk + b * PS + j0) = make_float4(s[0], s[1], s[2], s[3]);
    }
}

__global__ void __launch_bounds__(THREADS, 1) snn_ffma2(
    const float* __restrict__ x,
    const float* __restrict__ w1, const float* __restrict__ b1,
    const float* __restrict__ w2, const float* __restrict__ b2,
    const float* __restrict__ w3, const float* __restrict__ b3,
    const float* __restrict__ w4, const float* __restrict__ b4,
    float* __restrict__ out)
{
    extern __shared__ float sm[];
    float* xe  = sm + OFF_XE;
    float* sa  = sm + OFF_SA;
    float* sb  = sm + OFF_SB;
    float* us  = sm + OFF_US;
    float* w4s = sm + OFF_W4;

    const int tid = threadIdx.x;
    const int cg  = tid & 63;          // colgroup
    const int rg  = tid >> 6;          // rowgroup 0..6
    const int j0   = cg * 4;
    const int row0 = rg * 4;
    const int b0   = blockIdx.x * MB;

    // Init u state + stage w4.
    for (int idx = tid; idx < 3 * MB * Hh; idx += THREADS) us[idx] = 0.0f;
    w4s[tid] = w4[tid];
    if (tid < Hh * Aa - THREADS) w4s[THREADS + tid] = w4[THREADS + tid];

    float vm1[4][4], vm2[4][4], vm3[4][4];
#pragma unroll
    for (int r = 0; r < 4; ++r)
#pragma unroll
        for (int c = 0; c < 4; ++c) { vm1[r][c] = 0.f; vm2[r][c] = 0.f; vm3[r][c] = 0.f; }

    const float4 bias1 = *reinterpret_cast<const float4*>(b1 + j0);
    const float4 bias2 = *reinterpret_cast<const float4*>(b2 + j0);
    const float4 bias3 = *reinterpret_cast<const float4*>(b3 + j0);

    // Layer 4: threads 0..55 own (row, action).
    const int l4b = tid >> 1;
    const int l4a = tid & 1;
    float u4 = 0.f, v4m = 0.f, s4sum = 0.f, bias4 = 0.f;
    if (tid < MB * Aa) bias4 = b4[l4a];

    for (int t = 0; t < Tt; ++t) {
        // Stage x[:, :, t] and x[:, :, t+1] on even t (adjacent in memory).
        if ((t & 1) == 0) {
#pragma unroll
            for (int it = 0; it < (MB * Ss) / THREADS; ++it) {
                const int idx = tid + it * THREADS;
                const int i = idx >> 8;
                const int s = idx & 255;
                int bg = b0 + i;
                if (bg >= Bb) bg = Bb - 1;
                const float2 p = *reinterpret_cast<const float2*>(
                    &x[((size_t)bg * Ss + s) * (size_t)Tt + t]);
                xe[i * PS + s]           = p.x;
                xe[MB * PS + i * PS + s] = p.y;
            }
        }
        __syncthreads();  // staging visible; prior L4 done reading sa

        lif4x4(w1, bias1, xe + (t & 1) * MB * PS, sa, us + 0 * MB * Hh, vm1, row0, j0);
        __syncthreads();
        lif4x4(w2, bias2, sa, sb, us + 1 * MB * Hh, vm2, row0, j0);
        __syncthreads();
        lif4x4(w3, bias3, sb, sa, us + 2 * MB * Hh, vm3, row0, j0);
        __syncthreads();

        // Layer 4: [MB,256]@[256,2] + LIF + spike accumulation (56 threads).
        if (tid < MB * Aa) {
            float acc = 0.0f;
            const float4* row4 = reinterpret_cast<const float4*>(sa + l4b * PS);
#pragma unroll 4
            for (int k4 = 0; k4 < Hh / 4; ++k4) {
                const float4 p = row4[k4];
                acc = __fmaf_rn(p.x, w4s[(4 * k4 + 0) * Aa + l4a], acc);
                acc = __fmaf_rn(p.y, w4s[(4 * k4 + 1) * Aa + l4a], acc);
                acc = __fmaf_rn(p.z, w4s[(4 * k4 + 2) * Aa + l4a], acc);
                acc = __fmaf_rn(p.w, w4s[(4 * k4 + 3) * Aa + l4a], acc);
            }
            const float cur  = __fadd_rn(__fadd_rn(__fmul_rn(u4, CDECAY), acc), bias4);
            const float volt = __fadd_rn(v4m, cur);
            const float s    = (volt > VTH) ? 1.0f : 0.0f;
            u4  = cur;
            v4m = __fmul_rn(__fmul_rn(volt, VDECAY), __fsub_rn(1.0f, s));
            s4sum = __fadd_rn(s4sum, s);
        }
    }

    if (tid < MB * Aa) {
        const int bg = b0 + l4b;
        if (bg < Bb) {
            out[bg * Aa + l4a] =
                __fdiv_rn(__fdiv_rn(s4sum, (float)Tt), (float)Tt);
        }
    }
}

extern "C" void kernel_launch(void* const* d_in, const int* in_sizes, int n_in,
                              void* d_out, int out_size)
{
    const float* x  = (const float*)d_in[0];
    const float* w1 = (const float*)d_in[1];
    const float* b1 = (const float*)d_in[2];
    const float* w2 = (const float*)d_in[3];
    const float* b2 = (const float*)d_in[4];
    const float* w3 = (const float*)d_in[5];
    const float* b3 = (const float*)d_in[6];
    const float* w4 = (const float*)d_in[7];
    const float* b4 = (const float*)d_in[8];
    float* out = (float*)d_out;
    (void)in_sizes; (void)n_in; (void)out_size;

    cudaFuncSetAttribute(snn_ffma2,
                         cudaFuncAttributeMaxDynamicSharedMemorySize,
                         SMEM_BYTES);

    snn_ffma2<<<NBLK, THREADS, SMEM_BYTES>>>(x, w1, b1, w2, b2, w3, b3, w4, b4, out);
}

// round 3
// speedup vs baseline: 1.2275x; 1.2275x over previous
#include <cuda_runtime.h>
#include <cstdint>

// ---------------------------------------------------------------------------
// 4-layer LIF SNN scan (B=4096, S=H=256, T=50, A=2) on sm_103a.
// R3: scalar FFMA, 4col x 4row tiles per thread, W via LDG.128 (kills the
// 1.82cyc/LDG LSU floor that co-bound R1). 448 threads, MB=28, grid=147
// (one balanced wave). Numerics bit-identical to R1 (ascending-k chains).
// ---------------------------------------------------------------------------

namespace {

constexpr int Bb = 4096;
constexpr int Ss = 256;
constexpr int Tt = 50;
constexpr int Hh = 256;
constexpr int Aa = 2;

constexpr int MB      = 28;
constexpr int THREADS = 448;                // 64 colgroups(4 cols) x 7 rowgroups(4 rows)
constexpr int NBLK    = (Bb + MB - 1) / MB; // 147
constexpr int PS      = 256;

constexpr float CDECAY = 0.5f;
constexpr float VDECAY = 0.75f;
constexpr float VTH    = 0.5f;

// smem layout (floats)
constexpr int OFF_XE = 0;                      // x tiles   [2][MB][PS]
constexpr int OFF_SA = OFF_XE + 2 * MB * PS;   // spike A   [MB][PS]
constexpr int OFF_SB = OFF_SA + MB * PS;       // spike B   [MB][PS]
constexpr int OFF_US = OFF_SB + MB * PS;       // u state   [3][MB][Hh]
constexpr int OFF_W4 = OFF_US + 3 * MB * Hh;   // w4        [Hh*Aa]
constexpr int SMEM_FLOATS = OFF_W4 + Hh * Aa;
constexpr int SMEM_BYTES  = SMEM_FLOATS * 4;   // 202,752 B

}  // namespace

// One LIF layer tile: thread owns cols [j0, j0+4) x rows [row0, row0+4).
// acc[r][c] accumulated with a single FMA chain, k strictly ascending ->
// bit-identical to the R1 scalar reference path.
__device__ __forceinline__ void lif4x4(
    const float* __restrict__ W,     // [Hh][Hh] row-major (row k, col j)
    const float4 bias,               // b[j0..j0+4)
    const float* __restrict__ pre,   // smem [MB][PS]
    float*       __restrict__ spk,   // smem [MB][PS]
    float*       __restrict__ u_s,   // smem [MB][Hh] (this layer)
    float (&vm)[4][4],               // (v*0.75)*(1-s) carry, [row][col]
    int row0, int j0)
{
    float acc[4][4];
#pragma unroll
    for (int r = 0; r < 4; ++r)
#pragma unroll
        for (int c = 0; c < 4; ++c) acc[r][c] = 0.0f;

    const float* wp = W + j0;

#pragma unroll 2
    for (int k4 = 0; k4 < Hh / 4; ++k4) {
        // W rows k4*4 .. k4*4+3, 4 consecutive cols each: one LDG.128 per row.
        float4 wk[4];
#pragma unroll
        for (int kk = 0; kk < 4; ++kk)
            wk[kk] = __ldg(reinterpret_cast<const float4*>(wp + (k4 * 4 + kk) * Hh));

#pragma unroll
        for (int r = 0; r < 4; ++r) {
            const float4 p = *reinterpret_cast<const float4*>(pre + (row0 + r) * PS + k4 * 4);
#pragma unroll
            for (int c = 0; c < 4; ++c) {
                float a = acc[r][c];
                a = __fmaf_rn(p.x, (&wk[0].x)[c], a);
                a = __fmaf_rn(p.y, (&wk[1].x)[c], a);
                a = __fmaf_rn(p.z, (&wk[2].x)[c], a);
                a = __fmaf_rn(p.w, (&wk[3].x)[c], a);
                acc[r][c] = a;
            }
        }
    }

#pragma unroll
    for (int r = 0; r < 4; ++r) {
        const int b = row0 + r;
        const float4 uo = *reinterpret_cast<const float4*>(u_s + b * Hh + j0);
        const float uu[4] = {uo.x, uo.y, uo.z, uo.w};
        const float bb[4] = {bias.x, bias.y, bias.z, bias.w};
        float cur[4], s[4];
#pragma unroll
        for (int c = 0; c < 4; ++c) {
            cur[c] = __fadd_rn(__fadd_rn(__fmul_rn(uu[c], CDECAY), acc[r][c]), bb[c]);
            const float volt = __fadd_rn(vm[r][c], cur[c]);
            s[c] = (volt > VTH) ? 1.0f : 0.0f;
            vm[r][c] = __fmul_rn(__fmul_rn(volt, VDECAY), __fsub_rn(1.0f, s[c]));
        }
        *reinterpret_cast<float4*>(u_s + b * Hh + j0) = make_float4(cur[0], cur[1], cur[2], cur[3]);
        *reinterpret_cast<float4*>(spk + b * PS + j0) = make_float4(s[0], s[1], s[2], s[3]);
    }
}

__global__ void __launch_bounds__(THREADS, 1) snn_r3(
    const float* __restrict__ x,
    const float* __restrict__ w1, const float* __restrict__ b1,
    const float* __restrict__ w2, const float* __restrict__ b2,
    const float* __restrict__ w3, const float* __restrict__ b3,
    const float* __restrict__ w4, const float* __restrict__ b4,
    float* __restrict__ out)
{
    extern __shared__ float sm[];
    float* xe  = sm + OFF_XE;
    float* sa  = sm + OFF_SA;
    float* sb  = sm + OFF_SB;
    float* us  = sm + OFF_US;
    float* w4s = sm + OFF_W4;

    const int tid = threadIdx.x;
    const int cg  = tid & 63;          // colgroup -> warp lanes span cols (bcast LDS ok)
    const int rg  = tid >> 6;          // rowgroup 0..6
    const int j0   = cg * 4;
    const int row0 = rg * 4;
    const int b0   = blockIdx.x * MB;

    // Init u state + stage w4.
    for (int idx = tid; idx < 3 * MB * Hh; idx += THREADS) us[idx] = 0.0f;
    w4s[tid] = w4[tid];
    if (tid < Hh * Aa - THREADS) w4s[THREADS + tid] = w4[THREADS + tid];

    float vm1[4][4], vm2[4][4], vm3[4][4];
#pragma unroll
    for (int r = 0; r < 4; ++r)
#pragma unroll
        for (int c = 0; c < 4; ++c) { vm1[r][c] = 0.f; vm2[r][c] = 0.f; vm3[r][c] = 0.f; }

    const float4 bias1 = *reinterpret_cast<const float4*>(b1 + j0);
    const float4 bias2 = *reinterpret_cast<const float4*>(b2 + j0);
    const float4 bias3 = *reinterpret_cast<const float4*>(b3 + j0);

    // Layer 4: threads 0..55 own (row, action).
    const int l4b = tid >> 1;
    const int l4a = tid & 1;
    float u4 = 0.f, v4m = 0.f, s4sum = 0.f, bias4 = 0.f;
    if (tid < MB * Aa) bias4 = b4[l4a];

    for (int t = 0; t < Tt; ++t) {
        // Stage x[:, :, t] and x[:, :, t+1] on even t (adjacent in memory).
        if ((t & 1) == 0) {
#pragma unroll
            for (int it = 0; it < (MB * Ss) / THREADS; ++it) {
                const int idx = tid + it * THREADS;
                const int i = idx >> 8;
                const int s = idx & 255;
                int bg = b0 + i;
                if (bg >= Bb) bg = Bb - 1;  // phantom rows: harmless clamp
                const float2 p = *reinterpret_cast<const float2*>(
                    &x[((size_t)bg * Ss + s) * (size_t)Tt + t]);
                xe[i * PS + s]           = p.x;
                xe[MB * PS + i * PS + s] = p.y;
            }
        }
        __syncthreads();  // staging visible; prior L4 done reading sa

        lif4x4(w1, bias1, xe + (t & 1) * MB * PS, sa, us + 0 * MB * Hh, vm1, row0, j0);
        __syncthreads();
        lif4x4(w2, bias2, sa, sb, us + 1 * MB * Hh, vm2, row0, j0);
        __syncthreads();
        lif4x4(w3, bias3, sb, sa, us + 2 * MB * Hh, vm3, row0, j0);
        __syncthreads();

        // Layer 4: [MB,256]@[256,2] + LIF + spike accumulation (56 threads).
        if (tid < MB * Aa) {
            float acc = 0.0f;
            const float4* row4 = reinterpret_cast<const float4*>(sa + l4b * PS);
#pragma unroll 4
            for (int k4 = 0; k4 < Hh / 4; ++k4) {
                const float4 p = row4[k4];
                acc = __fmaf_rn(p.x, w4s[(4 * k4 + 0) * Aa + l4a], acc);
                acc = __fmaf_rn(p.y, w4s[(4 * k4 + 1) * Aa + l4a], acc);
                acc = __fmaf_rn(p.z, w4s[(4 * k4 + 2) * Aa + l4a], acc);
                acc = __fmaf_rn(p.w, w4s[(4 * k4 + 3) * Aa + l4a], acc);
            }
            const float cur  = __fadd_rn(__fadd_rn(__fmul_rn(u4, CDECAY), acc), bias4);
            const float volt = __fadd_rn(v4m, cur);
            const float s    = (volt > VTH) ? 1.0f : 0.0f;
            u4  = cur;
            v4m = __fmul_rn(__fmul_rn(volt, VDECAY), __fsub_rn(1.0f, s));
            s4sum = __fadd_rn(s4sum, s);
        }
    }

    if (tid < MB * Aa) {
        const int bg = b0 + l4b;
        if (bg < Bb) {
            out[bg * Aa + l4a] =
                __fdiv_rn(__fdiv_rn(s4sum, (float)Tt), (float)Tt);
        }
    }
}

extern "C" void kernel_launch(void* const* d_in, const int* in_sizes, int n_in,
                              void* d_out, int out_size)
{
    const float* x  = (const float*)d_in[0];
    const float* w1 = (const float*)d_in[1];
    const float* b1 = (const float*)d_in[2];
    const float* w2 = (const float*)d_in[3];
    const float* b2 = (const float*)d_in[4];
    const float* w3 = (const float*)d_in[5];
    const float* b3 = (const float*)d_in[6];
    const float* w4 = (const float*)d_in[7];
    const float* b4 = (const float*)d_in[8];
    float* out = (float*)d_out;
    (void)in_sizes; (void)n_in; (void)out_size;

    cudaFuncSetAttribute(snn_r3,
                         cudaFuncAttributeMaxDynamicSharedMemorySize,
                         SMEM_BYTES);

    snn_r3<<<NBLK, THREADS, SMEM_BYTES>>>(x, w1, b1, w2, b2, w3, b3, w4, b4, out);
}

// round 4
// speedup vs baseline: 1.7710x; 1.4427x over previous
#include <cuda_runtime.h>
#include <cstdint>

// ---------------------------------------------------------------------------
// 4-layer LIF SNN scan (B=4096, S=H=256, T=50, A=2) on sm_103a.
// R4: W staged through smem via cp.async double-buffered 16-row chunks
// (kills exposed L1/L2 load latency that bound R3). Scalar FFMA, 4x4 thread
// tiles, 448 threads, MB=28, grid=147 (one wave, 1 block/SM).
// Numerics bit-identical to R1/R3 (ascending-k single-accumulator chains).
// ---------------------------------------------------------------------------

namespace {

constexpr int Bb = 4096;
constexpr int Ss = 256;
constexpr int Tt = 50;
constexpr int Hh = 256;
constexpr int Aa = 2;

constexpr int MB      = 28;
constexpr int THREADS = 448;                // 64 colgroups(4) x 7 rowgroups(4)
constexpr int NBLK    = (Bb + MB - 1) / MB; // 147
constexpr int PS      = 256;

constexpr int KC = 16;                      // W rows per staged chunk
constexpr int NC = Hh / KC;                 // 16 chunks per layer

constexpr float CDECAY = 0.5f;
constexpr float VDECAY = 0.75f;
constexpr float VTH    = 0.5f;

// smem layout (floats)
constexpr int OFF_XE = 0;                       // x tile    [MB][PS]
constexpr int OFF_SA = OFF_XE + MB * PS;        // spike A   [MB][PS]
constexpr int OFF_SB = OFF_SA + MB * PS;        // spike B   [MB][PS]
constexpr int OFF_US = OFF_SB + MB * PS;        // u state   [3][MB][Hh]
constexpr int OFF_WB = OFF_US + 3 * MB * Hh;    // W chunks  [2][KC*Hh]
constexpr int OFF_W4 = OFF_WB + 2 * KC * Hh;    // w4        [Hh*Aa]
constexpr int SMEM_FLOATS = OFF_W4 + Hh * Aa;   // 51,712
constexpr int SMEM_BYTES  = SMEM_FLOATS * 4;    // 206,848 B

}  // namespace

__device__ __forceinline__ void cpa16(uint32_t dst_s, const void* src_g) {
    asm volatile("cp.async.cg.shared.global [%0], [%1], 16;\n"
                 :: "r"(dst_s), "l"(src_g));
}
__device__ __forceinline__ void cpa_commit() {
    asm volatile("cp.async.commit_group;\n");
}
__device__ __forceinline__ void cpa_wait0() {
    asm volatile("cp.async.wait_group 0;\n" ::: "memory");
}

// Issue async copy of W chunk c (KC rows x Hh cols) into smem buffer buf.
__device__ __forceinline__ void stage_chunk(const float* __restrict__ W, int c,
                                            float* buf, int tid) {
    const float4* src = reinterpret_cast<const float4*>(W + c * KC * Hh);
    uint32_t dst = (uint32_t)__cvta_generic_to_shared(buf);
#pragma unroll
    for (int i = 0; i < 3; ++i) {
        const int idx = tid + i * THREADS;
        if (idx < KC * Hh / 4) cpa16(dst + idx * 16, src + idx);
    }
    cpa_commit();
}

// One LIF layer: thread owns cols [j0,j0+4) x rows [row0,row0+4).
// W streamed through double-buffered smem chunks; ascending-k FMA chains.
__device__ __forceinline__ void lif4x4_s(
    const float* __restrict__ W,        // [Hh][Hh] gmem
    const float* __restrict__ bias_g,   // [Hh] gmem
    float*       __restrict__ wb,       // smem [2][KC*Hh]
    const float* __restrict__ pre,      // smem [MB][PS]
    float*       __restrict__ spk,      // smem [MB][PS]
    float*       __restrict__ u_s,      // smem [MB][Hh]
    float (&vm)[4][4],
    int row0, int j0, int tid)
{
    float acc[4][4];
#pragma unroll
    for (int r = 0; r < 4; ++r)
#pragma unroll
        for (int c = 0; c < 4; ++c) acc[r][c] = 0.0f;

    stage_chunk(W, 0, wb, tid);

    for (int c = 0; c < NC; ++c) {
        cpa_wait0();          // this thread's part of chunk c landed
        __syncthreads();      // whole chunk c visible; buf[(c+1)&1] free
        if (c + 1 < NC) stage_chunk(W, c + 1, wb + ((c + 1) & 1) * KC * Hh, tid);

        const float* wc = wb + (c & 1) * KC * Hh;
#pragma unroll
        for (int k4 = 0; k4 < KC / 4; ++k4) {
            float4 wk[4];
#pragma unroll
            for (int kk = 0; kk < 4; ++kk)
                wk[kk] = *reinterpret_cast<const float4*>(wc + (k4 * 4 + kk) * Hh + j0);
#pragma unroll
            for (int r = 0; r < 4; ++r) {
                const float4 p = *reinterpret_cast<const float4*>(
                    pre + (row0 + r) * PS + c * KC + k4 * 4);
#pragma unroll
                for (int cc = 0; cc < 4; ++cc) {
                    float a = acc[r][cc];
                    a = __fmaf_rn(p.x, (&wk[0].x)[cc], a);
                    a = __fmaf_rn(p.y, (&wk[1].x)[cc], a);
                    a = __fmaf_rn(p.z, (&wk[2].x)[cc], a);
                    a = __fmaf_rn(p.w, (&wk[3].x)[cc], a);
                    acc[r][cc] = a;
                }
            }
        }
    }

    const float4 bias = *reinterpret_cast<const float4*>(bias_g + j0);
#pragma unroll
    for (int r = 0; r < 4; ++r) {
        const int b = row0 + r;
        const float4 uo = *reinterpret_cast<const float4*>(u_s + b * Hh + j0);
        const float uu[4] = {uo.x, uo.y, uo.z, uo.w};
        const float bb[4] = {bias.x, bias.y, bias.z, bias.w};
        float cur[4], s[4];
#pragma unroll
        for (int cc = 0; cc < 4; ++cc) {
            cur[cc] = __fadd_rn(__fadd_rn(__fmul_rn(uu[cc], CDECAY), acc[r][cc]), bb[cc]);
            const float volt = __fadd_rn(vm[r][cc], cur[cc]);
            s[cc] = (volt > VTH) ? 1.0f : 0.0f;
            vm[r][cc] = __fmul_rn(__fmul_rn(volt, VDECAY), __fsub_rn(1.0f, s[cc]));
        }
        *reinterpret_cast<float4*>(u_s + b * Hh + j0) = make_float4(cur[0], cur[1], cur[2], cur[3]);
        *reinterpret_cast<float4*>(spk + b * PS + j0) = make_float4(s[0], s[1], s[2], s[3]);
    }
}

__global__ void __launch_bounds__(THREADS, 1) snn_r4(
    const float* __restrict__ x,
    const float* __restrict__ w1, const float* __restrict__ b1,
    const float* __restrict__ w2, const float* __restrict__ b2,
    const float* __restrict__ w3, const float* __restrict__ b3,
    const float* __restrict__ w4, const float* __restrict__ b4,
    float* __restrict__ out)
{
    extern __shared__ float sm[];
    float* xe  = sm + OFF_XE;
    float* sa  = sm + OFF_SA;
    float* sb  = sm + OFF_SB;
    float* us  = sm + OFF_US;
    float* wb  = sm + OFF_WB;
    float* w4s = sm + OFF_W4;

    const int tid  = threadIdx.x;
    const int j0   = (tid & 63) * 4;   // warp lanes span columns
    const int row0 = (tid >> 6) * 4;   // rowgroup uniform per warp
    const int b0   = blockIdx.x * MB;

    for (int idx = tid; idx < 3 * MB * Hh; idx += THREADS) us[idx] = 0.0f;
    w4s[tid] = w4[tid];
    if (tid < Hh * Aa - THREADS) w4s[THREADS + tid] = w4[THREADS + tid];

    float vm1[4][4], vm2[4][4], vm3[4][4];
#pragma unroll
    for (int r = 0; r < 4; ++r)
#pragma unroll
        for (int c = 0; c < 4; ++c) { vm1[r][c] = 0.f; vm2[r][c] = 0.f; vm3[r][c] = 0.f; }

    // Layer 4: threads 0..55 own (row, action).
    const int l4b = tid >> 1;
    const int l4a = tid & 1;
    float u4 = 0.f, v4m = 0.f, s4sum = 0.f, bias4 = 0.f;
    if (tid < MB * Aa) bias4 = b4[l4a];

    for (int t = 0; t < Tt; ++t) {
        __syncthreads();   // L4 done with sa; xe free for restage

        // Stage x[:, :, t]: aligned float2 over (t even base), pick half.
        {
            const int t0 = t & ~1;
#pragma unroll
            for (int it = 0; it < (MB * Ss) / THREADS; ++it) {
                const int idx = tid + it * THREADS;
                const int i = idx >> 8;
                const int s = idx & 255;
                int bg = b0 + i;
                if (bg >= Bb) bg = Bb - 1;  // phantom rows: harmless
                const float2 p = *reinterpret_cast<const float2*>(
                    &x[((size_t)bg * Ss + s) * (size_t)Tt + t0]);
                xe[i * PS + s] = (t & 1) ? p.y : p.x;
            }
        }
        // (xe visibility to all threads is covered by layer1's first internal sync)

        lif4x4_s(w1, b1, wb, xe, sa, us + 0 * MB * Hh, vm1, row0, j0, tid);
        __syncthreads();
        lif4x4_s(w2, b2, wb, sa, sb, us + 1 * MB * Hh, vm2, row0, j0, tid);
        __syncthreads();
        lif4x4_s(w3, b3, wb, sb, sa, us + 2 * MB * Hh, vm3, row0, j0, tid);
        __syncthreads();

        // Layer 4: [MB,256]@[256,2] + LIF + spike accumulation (56 threads).
        if (tid < MB * Aa) {
            float acc = 0.0f;
            const float4* row4 = reinterpret_cast<const float4*>(sa + l4b * PS);
#pragma unroll 4
            for (int k4 = 0; k4 < Hh / 4; ++k4) {
                const float4 p = row4[k4];
                acc = __fmaf_rn(p.x, w4s[(4 * k4 + 0) * Aa + l4a], acc);
                acc = __fmaf_rn(p.y, w4s[(4 * k4 + 1) * Aa + l4a], acc);
                acc = __fmaf_rn(p.z, w4s[(4 * k4 + 2) * Aa + l4a], acc);
                acc = __fmaf_rn(p.w, w4s[(4 * k4 + 3) * Aa + l4a], acc);
            }
            const float cur  = __fadd_rn(__fadd_rn(__fmul_rn(u4, CDECAY), acc), bias4);
            const float volt = __fadd_rn(v4m, cur);
            const float s    = (volt > VTH) ? 1.0f : 0.0f;
            u4  = cur;
            v4m = __fmul_rn(__fmul_rn(volt, VDECAY), __fsub_rn(1.0f, s));
            s4sum = __fadd_rn(s4sum, s);
        }
    }

    if (tid < MB * Aa) {
        const int bg = b0 + l4b;
        if (bg < Bb) {
            out[bg * Aa + l4a] =
                __fdiv_rn(__fdiv_rn(s4sum, (float)Tt), (float)Tt);
        }
    }
}

extern "C" void kernel_launch(void* const* d_in, const int* in_sizes, int n_in,
                              void* d_out, int out_size)
{
    const float* x  = (const float*)d_in[0];
    const float* w1 = (const float*)d_in[1];
    const float* b1 = (const float*)d_in[2];
    const float* w2 = (const float*)d_in[3];
    const float* b2 = (const float*)d_in[4];
    const float* w3 = (const float*)d_in[5];
    const float* b3 = (const float*)d_in[6];
    const float* w4 = (const float*)d_in[7];
    const float* b4 = (const float*)d_in[8];
    float* out = (float*)d_out;
    (void)in_sizes; (void)n_in; (void)out_size;

    cudaFuncSetAttribute(snn_r4,
                         cudaFuncAttributeMaxDynamicSharedMemorySize,
                         SMEM_BYTES);

    snn_r4<<<NBLK, THREADS, SMEM_BYTES>>>(x, w1, b1, w2, b2, w3, b3, w4, b4, out);
}

// round 5
// speedup vs baseline: 1.7939x; 1.0129x over previous
#include <cuda_runtime.h>
#include <cstdint>

// ---------------------------------------------------------------------------
// 4-layer LIF SNN scan (B=4096, S=H=256, T=50, A=2) on sm_103a.
// R5: 2 CTAs/SM (MB=14, 256 thr, grid=293) so barrier drains in one CTA are
// hidden by the other; x loaded with __ldcs (evict-first) so the x stream
// stops evicting W from L2 (R4's DRAM=22% was W re-missing to DRAM).
// W staged via cp.async double-buffered KC=8 chunks. 2col x 7row tiles.
// Numerics bit-identical: per-(b,j) single FMA chain, k strictly ascending.
// ---------------------------------------------------------------------------

namespace {

constexpr int Bb = 4096;
constexpr int Ss = 256;
constexpr int Tt = 50;
constexpr int Hh = 256;
constexpr int Aa = 2;

constexpr int MB      = 14;
constexpr int THREADS = 256;                 // 128 colgroups(2) x 2 rowgroups(7)
constexpr int NBLK    = (Bb + MB - 1) / MB;  // 293
constexpr int PS      = 256;

constexpr int KC = 8;                        // W rows per staged chunk
constexpr int NC = Hh / KC;                  // 32 chunks per layer

constexpr float CDECAY = 0.5f;
constexpr float VDECAY = 0.75f;
constexpr float VTH    = 0.5f;

// smem layout (floats)
constexpr int OFF_XE = 0;                        // x tile    [MB][PS]
constexpr int OFF_SA = OFF_XE + MB * PS;         // spike A   [MB][PS]
constexpr int OFF_SB = OFF_SA + MB * PS;         // spike B   [MB][PS]
constexpr int OFF_US = OFF_SB + MB * PS;         // u state   [3][MB][Hh]
constexpr int OFF_WB = OFF_US + 3 * MB * Hh;     // W chunks  [2][KC*Hh]
constexpr int OFF_W4 = OFF_WB + 2 * KC * Hh;     // w4        [Hh*Aa]
constexpr int SMEM_FLOATS = OFF_W4 + Hh * Aa;    // 26,112
constexpr int SMEM_BYTES  = SMEM_FLOATS * 4;     // 104,448 B (2 CTAs/SM fit)

}  // namespace

__device__ __forceinline__ void cpa16(uint32_t dst_s, const void* src_g) {
    asm volatile("cp.async.cg.shared.global [%0], [%1], 16;\n"
                 :: "r"(dst_s), "l"(src_g));
}
__device__ __forceinline__ void cpa_commit() {
    asm volatile("cp.async.commit_group;\n");
}
__device__ __forceinline__ void cpa_wait0() {
    asm volatile("cp.async.wait_group 0;\n" ::: "memory");
}

// Evict-first (streaming) float2 load for x.
__device__ __forceinline__ float2 ldcs2(const float* p) {
    float2 r;
    asm volatile("ld.global.cs.v2.f32 {%0, %1}, [%2];"
                 : "=f"(r.x), "=f"(r.y) : "l"(p));
    return r;
}

// Issue async copy of W chunk c (KC rows x Hh cols): 512 float4 / 256 thr = 2 each.
__device__ __forceinline__ void stage_chunk(const float* __restrict__ W, int c,
                                            float* buf, int tid) {
    const float4* src = reinterpret_cast<const float4*>(W + c * KC * Hh);
    uint32_t dst = (uint32_t)__cvta_generic_to_shared(buf);
#pragma unroll
    for (int i = 0; i < (KC * Hh / 4) / THREADS; ++i) {
        const int idx = tid + i * THREADS;
        cpa16(dst + idx * 16, src + idx);
    }
    cpa_commit();
}

// One LIF layer: thread owns cols [j0,j0+2) x rows [row0,row0+7).
__device__ __forceinline__ void lif2x7(
    const float* __restrict__ W,        // [Hh][Hh] gmem
    const float* __restrict__ bias_g,   // [Hh] gmem
    float*       __restrict__ wb,       // smem [2][KC*Hh]
    const float* __restrict__ pre,      // smem [MB][PS]
    float*       __restrict__ spk,      // smem [MB][PS]
    float*       __restrict__ u_s,      // smem [MB][Hh]
    float (&vm)[7][2],
    int row0, int j0, int tid)
{
    float acc[7][2];
#pragma unroll
    for (int r = 0; r < 7; ++r) { acc[r][0] = 0.0f; acc[r][1] = 0.0f; }

    stage_chunk(W, 0, wb, tid);

    for (int c = 0; c < NC; ++c) {
        cpa_wait0();          // chunk c landed (this thread's part)
        __syncthreads();      // whole chunk c visible; other buffer free
        if (c + 1 < NC) stage_chunk(W, c + 1, wb + ((c + 1) & 1) * KC * Hh, tid);

        const float* wc = wb + (c & 1) * KC * Hh;
#pragma unroll
        for (int k4 = 0; k4 < KC / 4; ++k4) {
            float2 wk[4];
#pragma unroll
            for (int kk = 0; kk < 4; ++kk)
                wk[kk] = *reinterpret_cast<const float2*>(wc + (k4 * 4 + kk) * Hh + j0);
#pragma unroll
            for (int r = 0; r < 7; ++r) {
                const float4 p = *reinterpret_cast<const float4*>(
                    pre + (row0 + r) * PS + c * KC + k4 * 4);
                float a0 = acc[r][0], a1 = acc[r][1];
                a0 = __fmaf_rn(p.x, wk[0].x, a0);  a1 = __fmaf_rn(p.x, wk[0].y, a1);
                a0 = __fmaf_rn(p.y, wk[1].x, a0);  a1 = __fmaf_rn(p.y, wk[1].y, a1);
                a0 = __fmaf_rn(p.z, wk[2].x, a0);  a1 = __fmaf_rn(p.z, wk[2].y, a1);
                a0 = __fmaf_rn(p.w, wk[3].x, a0);  a1 = __fmaf_rn(p.w, wk[3].y, a1);
                acc[r][0] = a0; acc[r][1] = a1;
            }
        }
    }

    const float2 bias = *reinterpret_cast<const float2*>(bias_g + j0);
#pragma unroll
    for (int r = 0; r < 7; ++r) {
        const int b = row0 + r;
        const float2 uo = *reinterpret_cast<const float2*>(u_s + b * Hh + j0);
        float cur[2], s[2];
        const float uu[2] = {uo.x, uo.y};
        const float bb[2] = {bias.x, bias.y};
#pragma unroll
        for (int cc = 0; cc < 2; ++cc) {
            cur[cc] = __fadd_rn(__fadd_rn(__fmul_rn(uu[cc], CDECAY), acc[r][cc]), bb[cc]);
            const float volt = __fadd_rn(vm[r][cc], cur[cc]);
            s[cc] = (volt > VTH) ? 1.0f : 0.0f;
            vm[r][cc] = __fmul_rn(__fmul_rn(volt, VDECAY), __fsub_rn(1.0f, s[cc]));
        }
        *reinterpret_cast<float2*>(u_s + b * Hh + j0) = make_float2(cur[0], cur[1]);
        *reinterpret_cast<float2*>(spk + b * PS + j0) = make_float2(s[0], s[1]);
    }
}

__global__ void __launch_bounds__(THREADS, 2) snn_r5(
    const float* __restrict__ x,
    const float* __restrict__ w1, const float* __restrict__ b1,
    const float* __restrict__ w2, const float* __restrict__ b2,
    const float* __restrict__ w3, const float* __restrict__ b3,
    const float* __restrict__ w4, const float* __restrict__ b4,
    float* __restrict__ out)
{
    extern __shared__ float sm[];
    float* xe  = sm + OFF_XE;
    float* sa  = sm + OFF_SA;
    float* sb  = sm + OFF_SB;
    float* us  = sm + OFF_US;
    float* wb  = sm + OFF_WB;
    float* w4s = sm + OFF_W4;

    const int tid  = threadIdx.x;
    const int j0   = (tid & 127) * 2;   // warp lanes span 64 consecutive cols
    const int row0 = (tid >> 7) * 7;    // rowgroup 0 or 1
    const int b0   = blockIdx.x * MB;

    for (int idx = tid; idx < 3 * MB * Hh; idx += THREADS) us[idx] = 0.0f;
    w4s[tid]           = w4[tid];
    w4s[tid + THREADS] = w4[tid + THREADS];

    float vm1[7][2], vm2[7][2], vm3[7][2];
#pragma unroll
    for (int r = 0; r < 7; ++r)
#pragma unroll
        for (int c = 0; c < 2; ++c) { vm1[r][c] = 0.f; vm2[r][c] = 0.f; vm3[r][c] = 0.f; }

    // Layer 4: threads 0..27 own (row, action).
    const int l4b = tid >> 1;
    const int l4a = tid & 1;
    float u4 = 0.f, v4m = 0.f, s4sum = 0.f, bias4 = 0.f;
    if (tid < MB * Aa) bias4 = b4[l4a];

    for (int t = 0; t < Tt; ++t) {
        __syncthreads();   // L4 done with sa; xe free for restage

        // Stage x[:, :, t]: evict-first (streaming) loads so x never evicts W
        // from L2. Aligned float2 at even t-base, keep the needed half.
        {
            const int t0 = t & ~1;
#pragma unroll
            for (int it = 0; it < (MB * Ss) / THREADS; ++it) {
                const int idx = tid + it * THREADS;
                const int i = idx >> 8;
                const int s = idx & 255;
                int bg = b0 + i;
                if (bg >= Bb) bg = Bb - 1;  // phantom rows: harmless
                const float2 p = ldcs2(&x[((size_t)bg * Ss + s) * (size_t)Tt + t0]);
                xe[i * PS + s] = (t & 1) ? p.y : p.x;
            }
        }
        // xe visibility covered by layer1's internal chunk-0 sync.

        lif2x7(w1, b1, wb, xe, sa, us + 0 * MB * Hh, vm1, row0, j0, tid);
        __syncthreads();
        lif2x7(w2, b2, wb, sa, sb, us + 1 * MB * Hh, vm2, row0, j0, tid);
        __syncthreads();
        lif2x7(w3, b3, wb, sb, sa, us + 2 * MB * Hh, vm3, row0, j0, tid);
        __syncthreads();

        // Layer 4: [MB,256]@[256,2] + LIF + spike accumulation (28 threads).
        if (tid < MB * Aa) {
            float acc = 0.0f;
            const float4* row4 = reinterpret_cast<const float4*>(sa + l4b * PS);
#pragma unroll 4
            for (int k4 = 0; k4 < Hh / 4; ++k4) {
                const float4 p = row4[k4];
                acc = __fmaf_rn(p.x, w4s[(4 * k4 + 0) * Aa + l4a], acc);
                acc = __fmaf_rn(p.y, w4s[(4 * k4 + 1) * Aa + l4a], acc);
                acc = __fmaf_rn(p.z, w4s[(4 * k4 + 2) * Aa + l4a], acc);
                acc = __fmaf_rn(p.w, w4s[(4 * k4 + 3) * Aa + l4a], acc);
            }
            const float cur  = __fadd_rn(__fadd_rn(__fmul_rn(u4, CDECAY), acc), bias4);
            const float volt = __fadd_rn(v4m, cur);
            const float s    = (volt > VTH) ? 1.0f : 0.0f;
            u4  = cur;
            v4m = __fmul_rn(__fmul_rn(volt, VDECAY), __fsub_rn(1.0f, s));
            s4sum = __fadd_rn(s4sum, s);
        }
    }

    if (tid < MB * Aa) {
        const int bg = b0 + l4b;
        if (bg < Bb) {
            out[bg * Aa + l4a] =
                __fdiv_rn(__fdiv_rn(s4sum, (float)Tt), (float)Tt);
        }
    }
}

extern "C" void kernel_launch(void* const* d_in, const int* in_sizes, int n_in,
                              void* d_out, int out_size)
{
    const float* x  = (const float*)d_in[0];
    const float* w1 = (const float*)d_in[1];
    const float* b1 = (const float*)d_in[2];
    const float* w2 = (const float*)d_in[3];
    const float* b2 = (const float*)d_in[4];
    const float* w3 = (const float*)d_in[5];
    const float* b3 = (const float*)d_in[6];
    const float* w4 = (const float*)d_in[7];
    const float* b4 = (const float*)d_in[8];
    float* out = (float*)d_out;
    (void)in_sizes; (void)n_in; (void)out_size;

    cudaFuncSetAttribute(snn_r5,
                         cudaFuncAttributeMaxDynamicSharedMemorySize,
                         SMEM_BYTES);

    snn_r5<<<NBLK, THREADS, SMEM_BYTES>>>(x, w1, b1, w2, b2, w3, b3, w4, b4, out);
}

// round 6
// speedup vs baseline: 1.9060x; 1.0625x over previous
#include <cuda_runtime.h>
#include <cstdint>

// ---------------------------------------------------------------------------
// 4-layer LIF SNN scan (B=4096, S=H=256, T=50, A=2) on sm_103a.
// R6: barrier-count attack. KC=16 W chunks (16 syncs/layer instead of 32),
// two ping-pong tile buffers (XB<->SA) to fit 2 CTAs/SM, redundant
// inter-layer syncs removed (next layer's chunk-0 barrier orders them).
// ~49 barriers/step vs ~100 in R5. 2col x 7row tiles, MB=14, grid=293.
// Numerics bit-identical: per-(b,j) single FMA chain, k strictly ascending.
// ---------------------------------------------------------------------------

namespace {

constexpr int Bb = 4096;
constexpr int Ss = 256;
constexpr int Tt = 50;
constexpr int Hh = 256;
constexpr int Aa = 2;

constexpr int MB      = 14;
constexpr int THREADS = 256;                 // 128 colgroups(2) x 2 rowgroups(7)
constexpr int NBLK    = (Bb + MB - 1) / MB;  // 293
constexpr int PS      = 256;

constexpr int KC = 16;                       // W rows per staged chunk
constexpr int NC = Hh / KC;                  // 16 chunks per layer

constexpr float CDECAY = 0.5f;
constexpr float VDECAY = 0.75f;
constexpr float VTH    = 0.5f;

// smem layout (floats)
constexpr int OFF_XB = 0;                        // tile buf X [MB][PS]
constexpr int OFF_SA = OFF_XB + MB * PS;         // tile buf A [MB][PS]
constexpr int OFF_US = OFF_SA + MB * PS;         // u state    [3][MB][Hh]
constexpr int OFF_WB = OFF_US + 3 * MB * Hh;     // W chunks   [2][KC*Hh]
constexpr int OFF_W4 = OFF_WB + 2 * KC * Hh;     // w4         [Hh*Aa]
constexpr int SMEM_FLOATS = OFF_W4 + Hh * Aa;    // 26,624
constexpr int SMEM_BYTES  = SMEM_FLOATS * 4;     // 106,496 B (2 CTAs/SM fit)

}  // namespace

__device__ __forceinline__ void cpa16(uint32_t dst_s, const void* src_g) {
    asm volatile("cp.async.cg.shared.global [%0], [%1], 16;\n"
                 :: "r"(dst_s), "l"(src_g));
}
__device__ __forceinline__ void cpa_commit() {
    asm volatile("cp.async.commit_group;\n");
}
__device__ __forceinline__ void cpa_wait0() {
    asm volatile("cp.async.wait_group 0;\n" ::: "memory");
}

// Evict-first (streaming) float2 load for x.
__device__ __forceinline__ float2 ldcs2(const float* p) {
    float2 r;
    asm volatile("ld.global.cs.v2.f32 {%0, %1}, [%2];"
                 : "=f"(r.x), "=f"(r.y) : "l"(p));
    return r;
}

// Async copy of W chunk c (KC rows x Hh cols): 1024 float4 / 256 thr = 4 each.
__device__ __forceinline__ void stage_chunk(const float* __restrict__ W, int c,
                                            float* buf, int tid) {
    const float4* src = reinterpret_cast<const float4*>(W + c * KC * Hh);
    uint32_t dst = (uint32_t)__cvta_generic_to_shared(buf);
#pragma unroll
    for (int i = 0; i < (KC * Hh / 4) / THREADS; ++i) {
        const int idx = tid + i * THREADS;
        cpa16(dst + idx * 16, src + idx);
    }
    cpa_commit();
}

// One LIF layer: thread owns cols [j0,j0+2) x rows [row0,row0+7).
// First chunk barrier also orders the previous producer's smem stores.
__device__ __forceinline__ void lif2x7(
    const float* __restrict__ W,        // [Hh][Hh] gmem
    const float* __restrict__ bias_g,   // [Hh] gmem
    float*       __restrict__ wb,       // smem [2][KC*Hh]
    const float* __restrict__ pre,      // smem [MB][PS]
    float*       __restrict__ spk,      // smem [MB][PS]
    float*       __restrict__ u_s,      // smem [MB][Hh]
    float (&vm)[7][2],
    int row0, int j0, int tid)
{
    float acc[7][2];
#pragma unroll
    for (int r = 0; r < 7; ++r) { acc[r][0] = 0.0f; acc[r][1] = 0.0f; }

    stage_chunk(W, 0, wb, tid);

    for (int c = 0; c < NC; ++c) {
        cpa_wait0();          // chunk c landed (this thread's part)
        __syncthreads();      // whole chunk c visible; other buffer free
        if (c + 1 < NC) stage_chunk(W, c + 1, wb + ((c + 1) & 1) * KC * Hh, tid);

        const float* wc = wb + (c & 1) * KC * Hh;
#pragma unroll
        for (int k4 = 0; k4 < KC / 4; ++k4) {
            float2 wk[4];
#pragma unroll
            for (int kk = 0; kk < 4; ++kk)
                wk[kk] = *reinterpret_cast<const float2*>(wc + (k4 * 4 + kk) * Hh + j0);
#pragma unroll
            for (int r = 0; r < 7; ++r) {
                const float4 p = *reinterpret_cast<const float4*>(
                    pre + (row0 + r) * PS + c * KC + k4 * 4);
                float a0 = acc[r][0], a1 = acc[r][1];
                a0 = __fmaf_rn(p.x, wk[0].x, a0);  a1 = __fmaf_rn(p.x, wk[0].y, a1);
                a0 = __fmaf_rn(p.y, wk[1].x, a0);  a1 = __fmaf_rn(p.y, wk[1].y, a1);
                a0 = __fmaf_rn(p.z, wk[2].x, a0);  a1 = __fmaf_rn(p.z, wk[2].y, a1);
                a0 = __fmaf_rn(p.w, wk[3].x, a0);  a1 = __fmaf_rn(p.w, wk[3].y, a1);
                acc[r][0] = a0; acc[r][1] = a1;
            }
        }
    }

    const float2 bias = *reinterpret_cast<const float2*>(bias_g + j0);
#pragma unroll
    for (int r = 0; r < 7; ++r) {
        const int b = row0 + r;
        const float2 uo = *reinterpret_cast<const float2*>(u_s + b * Hh + j0);
        float cur[2], s[2];
        const float uu[2] = {uo.x, uo.y};
        const float bb[2] = {bias.x, bias.y};
#pragma unroll
        for (int cc = 0; cc < 2; ++cc) {
            cur[cc] = __fadd_rn(__fadd_rn(__fmul_rn(uu[cc], CDECAY), acc[r][cc]), bb[cc]);
            const float volt = __fadd_rn(vm[r][cc], cur[cc]);
            s[cc] = (volt > VTH) ? 1.0f : 0.0f;
            vm[r][cc] = __fmul_rn(__fmul_rn(volt, VDECAY), __fsub_rn(1.0f, s[cc]));
        }
        *reinterpret_cast<float2*>(u_s + b * Hh + j0) = make_float2(cur[0], cur[1]);
        *reinterpret_cast<float2*>(spk + b * PS + j0) = make_float2(s[0], s[1]);
    }
}

__global__ void __launch_bounds__(THREADS, 2) snn_r6(
    const float* __restrict__ x,
    const float* __restrict__ w1, const float* __restrict__ b1,
    const float* __restrict__ w2, const float* __restrict__ b2,
    const float* __restrict__ w3, const float* __restrict__ b3,
    const float* __restrict__ w4, const float* __restrict__ b4,
    float* __restrict__ out)
{
    extern __shared__ float sm[];
    float* xb  = sm + OFF_XB;
    float* sa  = sm + OFF_SA;
    float* us  = sm + OFF_US;
    float* wb  = sm + OFF_WB;
    float* w4s = sm + OFF_W4;

    const int tid  = threadIdx.x;
    const int j0   = (tid & 127) * 2;   // warp lanes span 64 consecutive cols
    const int row0 = (tid >> 7) * 7;    // rowgroup 0 or 1
    const int b0   = blockIdx.x * MB;

    for (int idx = tid; idx < 3 * MB * Hh; idx += THREADS) us[idx] = 0.0f;
    w4s[tid]           = w4[tid];
    w4s[tid + THREADS] = w4[tid + THREADS];

    float vm1[7][2], vm2[7][2], vm3[7][2];
#pragma unroll
    for (int r = 0; r < 7; ++r)
#pragma unroll
        for (int c = 0; c < 2; ++c) { vm1[r][c] = 0.f; vm2[r][c] = 0.f; vm3[r][c] = 0.f; }

    // Layer 4: threads 0..27 own (row, action).
    const int l4b = tid >> 1;
    const int l4a = tid & 1;
    float u4 = 0.f, v4m = 0.f, s4sum = 0.f, bias4 = 0.f;
    if (tid < MB * Aa) bias4 = b4[l4a];

    for (int t = 0; t < Tt; ++t) {
        // Stage x[:, :, t] into XB (free: L3 readers drained at the pre-L4
        // barrier of the previous step; L4 only touches SA).
        {
            const int t0 = t & ~1;
#pragma unroll
            for (int it = 0; it < (MB * Ss) / THREADS; ++it) {
                const int idx = tid + it * THREADS;
                const int i = idx >> 8;
                const int s = idx & 255;
                int bg = b0 + i;
                if (bg >= Bb) bg = Bb - 1;  // phantom rows: harmless
                const float2 p = ldcs2(&x[((size_t)bg * Ss + s) * (size_t)Tt + t0]);
                xb[i * PS + s] = (t & 1) ? p.y : p.x;
            }
        }
        // Visibility of xb / previous layer's spikes: covered by each layer's
        // chunk-0 __syncthreads inside lif2x7.

        lif2x7(w1, b1, wb, xb, sa, us + 0 * MB * Hh, vm1, row0, j0, tid);
        lif2x7(w2, b2, wb, sa, xb, us + 1 * MB * Hh, vm2, row0, j0, tid);
        lif2x7(w3, b3, wb, xb, sa, us + 2 * MB * Hh, vm3, row0, j0, tid);
        __syncthreads();   // all SA spike stores visible before L4 reads

        // Layer 4: [MB,256]@[256,2] + LIF + spike accumulation (28 threads).
        if (tid < MB * Aa) {
            float acc = 0.0f;
            const float4* row4 = reinterpret_cast<const float4*>(sa + l4b * PS);
#pragma unroll 4
            for (int k4 = 0; k4 < Hh / 4; ++k4) {
                const float4 p = row4[k4];
                acc = __fmaf_rn(p.x, w4s[(4 * k4 + 0) * Aa + l4a], acc);
                acc = __fmaf_rn(p.y, w4s[(4 * k4 + 1) * Aa + l4a], acc);
                acc = __fmaf_rn(p.z, w4s[(4 * k4 + 2) * Aa + l4a], acc);
                acc = __fmaf_rn(p.w, w4s[(4 * k4 + 3) * Aa + l4a], acc);
            }
            const float cur  = __fadd_rn(__fadd_rn(__fmul_rn(u4, CDECAY), acc), bias4);
            const float volt = __fadd_rn(v4m, cur);
            const float s    = (volt > VTH) ? 1.0f : 0.0f;
            u4  = cur;
            v4m = __fmul_rn(__fmul_rn(volt, VDECAY), __fsub_rn(1.0f, s));
            s4sum = __fadd_rn(s4sum, s);
        }
    }

    if (tid < MB * Aa) {
        const int bg = b0 + l4b;
        if (bg < Bb) {
            out[bg * Aa + l4a] =
                __fdiv_rn(__fdiv_rn(s4sum, (float)Tt), (float)Tt);
        }
    }
}

extern "C" void kernel_launch(void* const* d_in, const int* in_sizes, int n_in,
                              void* d_out, int out_size)
{
    const float* x  = (const float*)d_in[0];
    const float* w1 = (const float*)d_in[1];
    const float* b1 = (const float*)d_in[2];
    const float* w2 = (const float*)d_in[3];
    const float* b2 = (const float*)d_in[4];
    const float* w3 = (const float*)d_in[5];
    const float* b3 = (const float*)d_in[6];
    const float* w4 = (const float*)d_in[7];
    const float* b4 = (const float*)d_in[8];
    float* out = (float*)d_out;
    (void)in_sizes; (void)n_in; (void)out_size;

    cudaFuncSetAttribute(snn_r6,
                         cudaFuncAttributeMaxDynamicSharedMemorySize,
                         SMEM_BYTES);

    snn_r6<<<NBLK, THREADS, SMEM_BYTES>>>(x, w1, b1, w2, b2, w3, b3, w4, b4, out);
}